// round 10
// baseline (speedup 1.0000x reference)
#include <cuda_runtime.h>
#include <cstdint>

// Problem constants
#define BB     64
#define SS     2048
#define INDIM  512
#define HH     512
#define CL     8            // cluster size (j-split of W_hh)
#define NCTA   128          // 16 clusters x 8 CTAs

typedef unsigned long long ull;

// ---------------- packed f32x2 helpers (FFMA2 path, sm_103a) ----------------
__device__ __forceinline__ void ffma2(ull& acc, ull a, ull b) {
    asm volatile("fma.rn.f32x2 %0, %1, %2, %0;" : "+l"(acc) : "l"(a), "l"(b));
}
__device__ __forceinline__ ull pack2(float x) {
    ull r; asm("mov.b64 %0, {%1, %1};" : "=l"(r) : "f"(x)); return r;
}
__device__ __forceinline__ ull packf2(float x, float y) {
    ull r; asm("mov.b64 %0, {%1, %2};" : "=l"(r) : "f"(x), "f"(y)); return r;
}
__device__ __forceinline__ float2 unpack2(ull v) {
    float2 r; asm("mov.b64 {%0, %1}, %2;" : "=f"(r.x), "=f"(r.y) : "l"(v)); return r;
}
__device__ __forceinline__ uint32_t smem_u32(const void* p) {
    uint32_t a;
    asm("{ .reg .u64 t; cvta.to.shared.u64 t, %1; cvt.u32.u64 %0, t; }" : "=r"(a) : "l"(p));
    return a;
}
__device__ __forceinline__ uint32_t mapa_rank(uint32_t laddr, uint32_t rank) {
    uint32_t r;
    asm("mapa.shared::cluster.u32 %0, %1, %2;" : "=r"(r) : "r"(laddr), "r"(rank));
    return r;
}
__device__ __forceinline__ void mbar_inval(uint32_t mbar) {
    asm volatile("mbarrier.inval.shared.b64 [%0];" :: "r"(mbar) : "memory");
}
__device__ __forceinline__ void mbar_init(uint32_t mbar, uint32_t cnt) {
    asm volatile("mbarrier.init.shared.b64 [%0], %1;" :: "r"(mbar), "r"(cnt) : "memory");
}
// per-thread release-arrive on a (possibly remote) cluster mbarrier:
// orders THIS thread's prior st.shared::cluster stores before the arrival.
__device__ __forceinline__ void mbar_arrive_remote(uint32_t raddr) {
    asm volatile("mbarrier.arrive.release.cluster.shared::cluster.b64 _, [%0];"
                 :: "r"(raddr) : "memory");
}
__device__ __forceinline__ void mbar_wait_cluster(uint32_t mbar, uint32_t parity) {
    asm volatile(
        "{\n\t.reg .pred P;\n\t"
        "WL_%=:\n\t"
        "mbarrier.try_wait.parity.acquire.cluster.shared::cta.b64 P, [%0], %1, 0x989680;\n\t"
        "@!P bra WL_%=;\n\t}"
        :: "r"(mbar), "r"(parity) : "memory");
}
// plain (weak) remote DSMEM store — direct crossbar, no async-proxy engine
__device__ __forceinline__ void st_cluster_b64(uint32_t raddr, ull v) {
    asm volatile("st.shared::cluster.b64 [%0], %1;" :: "r"(raddr), "l"(v) : "memory");
}

// ---------------- Phase 1: x_proj = inputs @ W_ih^T + b_ih ----------------
__global__ __launch_bounds__(256) void xproj_kernel(
    const float* __restrict__ A, const float* __restrict__ W,
    const float* __restrict__ bias, float* __restrict__ C) {
    __shared__ float As[16][132];
    __shared__ float Bs[16][132];

    const int tid = threadIdx.x;
    const int m0 = blockIdx.x * 128;
    const int n0 = blockIdx.y * 128;
    const int lr = tid >> 2;
    const int lk = (tid & 3) << 2;
    const int tx = tid & 15;
    const int ty = tid >> 4;

    ull acc[8][4];
#pragma unroll
    for (int i = 0; i < 8; i++)
#pragma unroll
        for (int j = 0; j < 4; j++) acc[i][j] = 0ull;

    for (int k0 = 0; k0 < INDIM; k0 += 16) {
        float4 a0 = *(const float4*)(A + (size_t)(m0 + lr) * INDIM + k0 + lk);
        float4 a1 = *(const float4*)(A + (size_t)(m0 + lr + 64) * INDIM + k0 + lk);
        float4 w0 = *(const float4*)(W + (size_t)(n0 + lr) * INDIM + k0 + lk);
        float4 w1 = *(const float4*)(W + (size_t)(n0 + lr + 64) * INDIM + k0 + lk);
        __syncthreads();
        As[lk + 0][lr] = a0.x; As[lk + 1][lr] = a0.y; As[lk + 2][lr] = a0.z; As[lk + 3][lr] = a0.w;
        As[lk + 0][lr + 64] = a1.x; As[lk + 1][lr + 64] = a1.y; As[lk + 2][lr + 64] = a1.z; As[lk + 3][lr + 64] = a1.w;
        Bs[lk + 0][lr] = w0.x; Bs[lk + 1][lr] = w0.y; Bs[lk + 2][lr] = w0.z; Bs[lk + 3][lr] = w0.w;
        Bs[lk + 0][lr + 64] = w1.x; Bs[lk + 1][lr + 64] = w1.y; Bs[lk + 2][lr + 64] = w1.z; Bs[lk + 3][lr + 64] = w1.w;
        __syncthreads();
#pragma unroll
        for (int k = 0; k < 16; k++) {
            float4 am0 = *(const float4*)&As[k][ty * 4];
            float4 am1 = *(const float4*)&As[k][64 + ty * 4];
            ulonglong2 bn0 = *(const ulonglong2*)&Bs[k][tx * 4];
            ulonglong2 bn1 = *(const ulonglong2*)&Bs[k][64 + tx * 4];
            float am[8] = {am0.x, am0.y, am0.z, am0.w, am1.x, am1.y, am1.z, am1.w};
#pragma unroll
            for (int i = 0; i < 8; i++) {
                ull ap = pack2(am[i]);
                ffma2(acc[i][0], ap, bn0.x);
                ffma2(acc[i][1], ap, bn0.y);
                ffma2(acc[i][2], ap, bn1.x);
                ffma2(acc[i][3], ap, bn1.y);
            }
        }
    }

    float4 bA = *(const float4*)(bias + n0 + tx * 4);
    float4 bBv = *(const float4*)(bias + n0 + 64 + tx * 4);
#pragma unroll
    for (int i = 0; i < 8; i++) {
        int m = m0 + ((i < 4) ? (ty * 4 + i) : (64 + ty * 4 + (i - 4)));
        float2 c0 = unpack2(acc[i][0]);
        float2 c1 = unpack2(acc[i][1]);
        float2 c2 = unpack2(acc[i][2]);
        float2 c3 = unpack2(acc[i][3]);
        float4 o0 = make_float4(c0.x + bA.x, c0.y + bA.y, c1.x + bA.z, c1.y + bA.w);
        float4 o1 = make_float4(c2.x + bBv.x, c2.y + bBv.y, c3.x + bBv.z, c3.y + bBv.w);
        *(float4*)(C + (size_t)m * HH + n0 + tx * 4) = o0;
        *(float4*)(C + (size_t)m * HH + n0 + 64 + tx * 4) = o1;
    }
}

// ---------------- Phase 2: scan — crossbar push + count-mbarrier sync ------
// Cluster of 8 CTAs = 4 batches in 2 groups of 2. Rank r owns j in
// [64r,64r+64); W slice in registers. Per phase: producers stage 64 ull in
// local smem; warp w ships the 512B slice to rank w with plain
// st.shared::cluster.b64 and each lane does mbarrier.arrive.release.cluster
// (release covers that lane's stores). Consumer: one TRYWAIT on a local
// count-256 mbarrier. No async engine, no fences, no expect_tx rearm.
__global__ __launch_bounds__(256, 1) __cluster_dims__(CL, 1, 1)
void rnn_scan_kernel(
    const float* __restrict__ h0, const float* __restrict__ W_hh,
    const float* __restrict__ b_hh, float* __restrict__ out, int write_hfinal) {
    __shared__ __align__(16) ull hsp[2][2][256][2];   // [grp][slot][kp][b] 16KB
    __shared__ float red[2][2][8][32][2];             // [grp][jpar][w][jp][b] 8KB
    __shared__ __align__(16) ull stg[2][2][64];       // [grp][slot][slice] 2KB
    __shared__ ull mbars[4];                          // [grp*2 + slot]

    const int tid = threadIdx.x;
    const int w = tid >> 5;           // warp: k-chunk for compute, dst rank for scatter
    const int l = tid & 31;           // lane -> j-pair {2l, 2l+1} in compute
    uint32_t rank;
    asm("mov.u32 %0, %%cluster_ctarank;" : "=r"(rank));
    const int j0 = (int)rank * 64;
    const int b0 = (blockIdx.x >> 3) * 4;
    const int obl = (tid >> 6) & 1;   // batch within group (tid<128 active)
    const int oj = tid & 63;          // j within slice
    const int gj = j0 + oj;

    // ---- W slice into registers, k-paired ----
    ull Wp0[32], Wp1[32];
    {
        const ull* w0p = (const ull*)(W_hh + (size_t)(j0 + 2 * l) * HH + w * 64);
        const ull* w1p = (const ull*)(W_hh + (size_t)(j0 + 2 * l + 1) * HH + w * 64);
#pragma unroll
        for (int p = 0; p < 32; p++) { Wp0[p] = w0p[p]; Wp1[p] = w1p[p]; }
    }
    const float bh = b_hh[gj];

    // ---- init h slot 0 of both groups from h0 ----
#pragma unroll
    for (int g = 0; g < 2; g++) {
        float* hf = (float*)&hsp[g][0][0][0];
        for (int i = tid; i < 2 * HH; i += 256) {
            int b = i >> 9, k = i & 511;
            hf[(k >> 1) * 4 + b * 2 + (k & 1)] = h0[(size_t)(b0 + 2 * g + b) * HH + k];
        }
    }

    const uint32_t mb_local = smem_u32(&mbars[0]);
    if (tid == 0) {
#pragma unroll
        for (int i = 0; i < 4; i++) {
            mbar_inval(mb_local + 8 * i);
            mbar_init(mb_local + 8 * i, 256u);   // 8 ranks x 32 lanes per phase
        }
        asm volatile("fence.mbarrier_init.release.cluster;" ::: "memory");
    }
    __syncthreads();
    asm volatile("barrier.cluster.arrive.aligned;" ::: "memory");
    asm volatile("barrier.cluster.wait.aligned;" ::: "memory");

    // warp-uniform remote bases: warp w targets rank w
    const uint32_t hbase = smem_u32(&hsp[0][0][0][0]);
    const uint32_t rwb = mapa_rank(hbase, (uint32_t)w);     // remote hsp base
    const uint32_t rwm = mapa_rank(mb_local, (uint32_t)w);  // remote mbar base
    // my slice lands at ull index 64*rank + 2l (+1) inside a (grp,slot) block
    const uint32_t doff = (uint32_t)((64 * (int)rank + 2 * l) * 8);

    const size_t obA = (size_t)(b0 + obl) * SS * HH + gj;
    const size_t obB = (size_t)(b0 + 2 + obl) * SS * HH + gj;
    float xpA = 0.f, xpB = 0.f, hlA = 0.f, hlB = 0.f;
    if (tid < 128) { xpA = __ldcs(out + obA); xpB = __ldcs(out + obB); }
    uint32_t phA0 = 0, phA1 = 0, phB0 = 0, phB1 = 0;

#define GSTEP(T, S, G, PH, XP, HL, OB)                                          \
  {                                                                             \
    if ((T) > 0) {                                                              \
      mbar_wait_cluster(mb_local + ((G) * 2 + (S)) * 8, PH);                    \
      PH ^= 1u;                                                                 \
    }                                                                           \
    const ull* hb = &hsp[G][S][w * 32][0];                                      \
    ull a00 = 0, a01 = 0, a10 = 0, a11 = 0;                                     \
    _Pragma("unroll")                                                           \
    for (int p = 0; p < 32; p++) {                                              \
      ulonglong2 hx = *(const ulonglong2*)(hb + p * 2);                         \
      ull w0 = Wp0[p], w1 = Wp1[p];                                             \
      ffma2(a00, hx.x, w0); ffma2(a01, hx.y, w0);                               \
      ffma2(a10, hx.x, w1); ffma2(a11, hx.y, w1);                               \
    }                                                                           \
    { float2 f; float2 ra, rb;                                                  \
      f = unpack2(a00); ra.x = f.x + f.y; f = unpack2(a01); ra.y = f.x + f.y;   \
      f = unpack2(a10); rb.x = f.x + f.y; f = unpack2(a11); rb.y = f.x + f.y;   \
      *(float2*)&red[G][0][w][l][0] = ra;                                       \
      *(float2*)&red[G][1][w][l][0] = rb; }                                     \
    __syncthreads();                                                            \
    float hv = 0.f;                                                             \
    if (tid < 128) {                                                            \
      const float* rf = &red[G][oj & 1][0][oj >> 1][obl];                       \
      float sum = rf[0] + rf[64] + rf[128] + rf[192]                            \
                + rf[256] + rf[320] + rf[384] + rf[448];                        \
      float pre = XP + sum + bh;                                                \
      float e = __expf(pre + pre);                                              \
      hv = 1.f - __fdividef(2.f, e + 1.f);                                      \
      float hvn = __shfl_down_sync(0xffffffffu, hv, 1);                         \
      if (!(oj & 1)) stg[G][S][(oj >> 1) * 2 + obl] = packf2(hv, hvn);          \
    }                                                                           \
    __syncthreads();                                                            \
    if ((T) + 1 < SS) {                                                         \
      ulonglong2 vs = *(const ulonglong2*)&stg[G][S][2 * l];                    \
      const uint32_t so = (uint32_t)(((G) * 2 + ((S) ^ 1)) * 4096) + doff;      \
      st_cluster_b64(rwb + so, vs.x);                                           \
      st_cluster_b64(rwb + so + 8, vs.y);                                       \
      mbar_arrive_remote(rwm + (uint32_t)(((G) * 2 + ((S) ^ 1)) * 8));          \
    }                                                                           \
    if (tid < 128) {                                                            \
      __stcs(out + OB + (size_t)(T) * HH, hv);                                  \
      HL = hv;                                                                  \
      if ((T) + 1 < SS) XP = __ldcs(out + OB + (size_t)((T) + 1) * HH);         \
    }                                                                           \
  }

    for (int t = 0; t < SS; t += 2) {
        GSTEP(t,     0, 0, phA0, xpA, hlA, obA);
        GSTEP(t,     0, 1, phB0, xpB, hlB, obB);
        GSTEP(t + 1, 1, 0, phA1, xpA, hlA, obA);
        GSTEP(t + 1, 1, 1, phB1, xpB, hlB, obB);
    }
#undef GSTEP

    if (write_hfinal && tid < 128) {
        out[(size_t)BB * SS * HH + (size_t)(b0 + obl) * HH + gj] = hlA;
        out[(size_t)BB * SS * HH + (size_t)(b0 + 2 + obl) * HH + gj] = hlB;
    }
    // leave mbarriers mid-phase; next launch invals + re-inits them
    asm volatile("barrier.cluster.arrive.aligned;" ::: "memory");
    asm volatile("barrier.cluster.wait.aligned;" ::: "memory");
}

// ---------------- launch ----------------
extern "C" void kernel_launch(void* const* d_in, const int* in_sizes, int n_in,
                              void* d_out, int out_size) {
    const float* inputs = (const float*)d_in[0];   // [64, 2048, 512]
    const float* h0     = (const float*)d_in[1];   // [64, 512]
    const float* W_ih   = (const float*)d_in[2];   // [512, 512]
    const float* W_hh   = (const float*)d_in[3];   // [512, 512]
    const float* b_ih   = (const float*)d_in[4];   // [512]
    const float* b_hh   = (const float*)d_in[5];   // [512]
    float* out = (float*)d_out;

    // Phase 1: x_proj into the outs region of d_out (scan overwrites in place)
    dim3 g1((BB * SS) / 128, HH / 128, 1);
    xproj_kernel<<<g1, 256>>>(inputs, W_ih, b_ih, out);

    // Phase 2: 16 clusters of 8 CTAs; crossbar push + count-mbarrier scan
    long long need = (long long)BB * SS * HH + (long long)BB * HH;
    int wf = ((long long)out_size >= need) ? 1 : 0;
    rnn_scan_kernel<<<NCTA, 256>>>(h0, W_hh, b_hh, out, wf);
}

// round 11
// speedup vs baseline: 1.1395x; 1.1395x over previous
#include <cuda_runtime.h>
#include <cstdint>

// Problem constants
#define BB     64
#define SS     2048
#define INDIM  512
#define HH     512
#define CL     8            // cluster size (j-split of W_hh)
#define NCTA   128          // 16 clusters x 8 CTAs

typedef unsigned long long ull;

// ---------------- packed f32x2 helpers (FFMA2 path, sm_103a) ----------------
__device__ __forceinline__ void ffma2(ull& acc, ull a, ull b) {
    asm volatile("fma.rn.f32x2 %0, %1, %2, %0;" : "+l"(acc) : "l"(a), "l"(b));
}
__device__ __forceinline__ ull pack2(float x) {
    ull r; asm("mov.b64 %0, {%1, %1};" : "=l"(r) : "f"(x)); return r;
}
__device__ __forceinline__ ull packf2(float x, float y) {
    ull r; asm("mov.b64 %0, {%1, %2};" : "=l"(r) : "f"(x), "f"(y)); return r;
}
__device__ __forceinline__ float2 unpack2(ull v) {
    float2 r; asm("mov.b64 {%0, %1}, %2;" : "=f"(r.x), "=f"(r.y) : "l"(v)); return r;
}
__device__ __forceinline__ uint32_t smem_u32(const void* p) {
    uint32_t a;
    asm("{ .reg .u64 t; cvta.to.shared.u64 t, %1; cvt.u32.u64 %0, t; }" : "=r"(a) : "l"(p));
    return a;
}
__device__ __forceinline__ uint32_t mapa_rank(uint32_t laddr, uint32_t rank) {
    uint32_t r;
    asm("mapa.shared::cluster.u32 %0, %1, %2;" : "=r"(r) : "r"(laddr), "r"(rank));
    return r;
}
__device__ __forceinline__ void mbar_inval(uint32_t mbar) {
    asm volatile("mbarrier.inval.shared.b64 [%0];" :: "r"(mbar) : "memory");
}
__device__ __forceinline__ void mbar_init(uint32_t mbar, uint32_t cnt) {
    asm volatile("mbarrier.init.shared.b64 [%0], %1;" :: "r"(mbar), "r"(cnt) : "memory");
}
// single release-arrive on a remote cluster mbarrier (one per rank per phase)
__device__ __forceinline__ void mbar_arrive_remote(uint32_t raddr) {
    asm volatile("mbarrier.arrive.release.cluster.shared::cluster.b64 _, [%0];"
                 :: "r"(raddr) : "memory");
}
__device__ __forceinline__ void mbar_wait_cluster(uint32_t mbar, uint32_t parity) {
    asm volatile(
        "{\n\t.reg .pred P;\n\t"
        "WL_%=:\n\t"
        "mbarrier.try_wait.parity.acquire.cluster.shared::cta.b64 P, [%0], %1, 0x989680;\n\t"
        "@!P bra WL_%=;\n\t}"
        :: "r"(mbar), "r"(parity) : "memory");
}
// plain (weak) remote DSMEM store — direct crossbar, no async-proxy engine
__device__ __forceinline__ void st_cluster_b64(uint32_t raddr, ull v) {
    asm volatile("st.shared::cluster.b64 [%0], %1;" :: "r"(raddr), "l"(v) : "memory");
}

// ---------------- Phase 1: x_proj = inputs @ W_ih^T + b_ih ----------------
__global__ __launch_bounds__(256) void xproj_kernel(
    const float* __restrict__ A, const float* __restrict__ W,
    const float* __restrict__ bias, float* __restrict__ C) {
    __shared__ float As[16][132];
    __shared__ float Bs[16][132];

    const int tid = threadIdx.x;
    const int m0 = blockIdx.x * 128;
    const int n0 = blockIdx.y * 128;
    const int lr = tid >> 2;
    const int lk = (tid & 3) << 2;
    const int tx = tid & 15;
    const int ty = tid >> 4;

    ull acc[8][4];
#pragma unroll
    for (int i = 0; i < 8; i++)
#pragma unroll
        for (int j = 0; j < 4; j++) acc[i][j] = 0ull;

    for (int k0 = 0; k0 < INDIM; k0 += 16) {
        float4 a0 = *(const float4*)(A + (size_t)(m0 + lr) * INDIM + k0 + lk);
        float4 a1 = *(const float4*)(A + (size_t)(m0 + lr + 64) * INDIM + k0 + lk);
        float4 w0 = *(const float4*)(W + (size_t)(n0 + lr) * INDIM + k0 + lk);
        float4 w1 = *(const float4*)(W + (size_t)(n0 + lr + 64) * INDIM + k0 + lk);
        __syncthreads();
        As[lk + 0][lr] = a0.x; As[lk + 1][lr] = a0.y; As[lk + 2][lr] = a0.z; As[lk + 3][lr] = a0.w;
        As[lk + 0][lr + 64] = a1.x; As[lk + 1][lr + 64] = a1.y; As[lk + 2][lr + 64] = a1.z; As[lk + 3][lr + 64] = a1.w;
        Bs[lk + 0][lr] = w0.x; Bs[lk + 1][lr] = w0.y; Bs[lk + 2][lr] = w0.z; Bs[lk + 3][lr] = w0.w;
        Bs[lk + 0][lr + 64] = w1.x; Bs[lk + 1][lr + 64] = w1.y; Bs[lk + 2][lr + 64] = w1.z; Bs[lk + 3][lr + 64] = w1.w;
        __syncthreads();
#pragma unroll
        for (int k = 0; k < 16; k++) {
            float4 am0 = *(const float4*)&As[k][ty * 4];
            float4 am1 = *(const float4*)&As[k][64 + ty * 4];
            ulonglong2 bn0 = *(const ulonglong2*)&Bs[k][tx * 4];
            ulonglong2 bn1 = *(const ulonglong2*)&Bs[k][64 + tx * 4];
            float am[8] = {am0.x, am0.y, am0.z, am0.w, am1.x, am1.y, am1.z, am1.w};
#pragma unroll
            for (int i = 0; i < 8; i++) {
                ull ap = pack2(am[i]);
                ffma2(acc[i][0], ap, bn0.x);
                ffma2(acc[i][1], ap, bn0.y);
                ffma2(acc[i][2], ap, bn1.x);
                ffma2(acc[i][3], ap, bn1.y);
            }
        }
    }

    float4 bA = *(const float4*)(bias + n0 + tx * 4);
    float4 bBv = *(const float4*)(bias + n0 + 64 + tx * 4);
#pragma unroll
    for (int i = 0; i < 8; i++) {
        int m = m0 + ((i < 4) ? (ty * 4 + i) : (64 + ty * 4 + (i - 4)));
        float2 c0 = unpack2(acc[i][0]);
        float2 c1 = unpack2(acc[i][1]);
        float2 c2 = unpack2(acc[i][2]);
        float2 c3 = unpack2(acc[i][3]);
        float4 o0 = make_float4(c0.x + bA.x, c0.y + bA.y, c1.x + bA.z, c1.y + bA.w);
        float4 o1 = make_float4(c2.x + bBv.x, c2.y + bBv.y, c3.x + bBv.z, c3.y + bBv.w);
        *(float4*)(C + (size_t)m * HH + n0 + tx * 4) = o0;
        *(float4*)(C + (size_t)m * HH + n0 + 64 + tx * 4) = o1;
    }
}

// ---------------- Phase 2: scan — register scatter + count-8 mbarriers -----
// Cluster of 8 CTAs = 4 batches in 2 groups of 2. Rank r owns j in
// [64r,64r+64); W slice in registers. Per GSTEP: producing threads fire 8
// plain st.shared::cluster.b64 straight from registers (no engine, no
// staging), __syncthreads, then threads 0-7 each issue ONE release-arrive on
// rank tid's count-8 mbarrier. Consumer: one acquire try_wait. 8 mbar events
// per phase per receiver — no contention, no async proxy, no fences.
__global__ __launch_bounds__(256, 1) __cluster_dims__(CL, 1, 1)
void rnn_scan_kernel(
    const float* __restrict__ h0, const float* __restrict__ W_hh,
    const float* __restrict__ b_hh, float* __restrict__ out, int write_hfinal) {
    __shared__ __align__(16) ull hsp[2][2][256][2];   // [grp][slot][kp][b] 16KB
    __shared__ float red[2][2][8][32][2];             // [grp][jpar][w][jp][b] 8KB
    __shared__ ull mbars[4];                          // [grp*2 + slot]

    const int tid = threadIdx.x;
    const int w = tid >> 5;           // warp -> k-chunk [64w, 64w+64)
    const int l = tid & 31;           // lane -> j-pair {2l, 2l+1}
    uint32_t rank;
    asm("mov.u32 %0, %%cluster_ctarank;" : "=r"(rank));
    const int j0 = (int)rank * 64;
    const int b0 = (blockIdx.x >> 3) * 4;
    const int obl = (tid >> 6) & 1;   // batch within group (tid<128 active)
    const int oj = tid & 63;          // j within slice
    const int gj = j0 + oj;

    // ---- W slice into registers, k-paired ----
    ull Wp0[32], Wp1[32];
    {
        const ull* w0p = (const ull*)(W_hh + (size_t)(j0 + 2 * l) * HH + w * 64);
        const ull* w1p = (const ull*)(W_hh + (size_t)(j0 + 2 * l + 1) * HH + w * 64);
#pragma unroll
        for (int p = 0; p < 32; p++) { Wp0[p] = w0p[p]; Wp1[p] = w1p[p]; }
    }
    const float bh = b_hh[gj];

    // ---- init h slot 0 of both groups from h0 ----
#pragma unroll
    for (int g = 0; g < 2; g++) {
        float* hf = (float*)&hsp[g][0][0][0];
        for (int i = tid; i < 2 * HH; i += 256) {
            int b = i >> 9, k = i & 511;
            hf[(k >> 1) * 4 + b * 2 + (k & 1)] = h0[(size_t)(b0 + 2 * g + b) * HH + k];
        }
    }

    const uint32_t mb_local = smem_u32(&mbars[0]);
    if (tid == 0) {
#pragma unroll
        for (int i = 0; i < 4; i++) {
            mbar_inval(mb_local + 8 * i);
            mbar_init(mb_local + 8 * i, 8u);   // one arrive per source rank
        }
        asm volatile("fence.mbarrier_init.release.cluster;" ::: "memory");
    }
    __syncthreads();
    asm volatile("barrier.cluster.arrive.aligned;" ::: "memory");
    asm volatile("barrier.cluster.wait.aligned;" ::: "memory");

    // remote addresses
    const uint32_t hbase = smem_u32(&hsp[0][0][0][0]);
    // producer data target: my (b, oj-pair) -> ull index (32*rank+(oj>>1))*2+obl
    const uint32_t myoff = (uint32_t)(((32 * (int)rank + (oj >> 1)) * 2 + obl) * 8);
    uint32_t rh[CL];
#pragma unroll
    for (int r = 0; r < CL; r++) rh[r] = mapa_rank(hbase, (uint32_t)r) + myoff;
    // arrive target for tid<8: rank 'tid's mbarrier array
    const uint32_t rma = mapa_rank(mb_local, (uint32_t)(tid & 7));

    const size_t obA = (size_t)(b0 + obl) * SS * HH + gj;
    const size_t obB = (size_t)(b0 + 2 + obl) * SS * HH + gj;
    float xpA = 0.f, xpB = 0.f, hlA = 0.f, hlB = 0.f;
    if (tid < 128) { xpA = __ldcs(out + obA); xpB = __ldcs(out + obB); }
    uint32_t phA0 = 0, phA1 = 0, phB0 = 0, phB1 = 0;

#define GSTEP(T, S, G, PH, XP, HL, OB)                                          \
  {                                                                             \
    if ((T) > 0) {                                                              \
      mbar_wait_cluster(mb_local + ((G) * 2 + (S)) * 8, PH);                    \
      PH ^= 1u;                                                                 \
    }                                                                           \
    const ull* hb = &hsp[G][S][w * 32][0];                                      \
    ull a00 = 0, a01 = 0, a10 = 0, a11 = 0;                                     \
    _Pragma("unroll")                                                           \
    for (int p = 0; p < 32; p++) {                                              \
      ulonglong2 hx = *(const ulonglong2*)(hb + p * 2);                         \
      ull w0 = Wp0[p], w1 = Wp1[p];                                             \
      ffma2(a00, hx.x, w0); ffma2(a01, hx.y, w0);                               \
      ffma2(a10, hx.x, w1); ffma2(a11, hx.y, w1);                               \
    }                                                                           \
    { float2 f; float2 ra, rb;                                                  \
      f = unpack2(a00); ra.x = f.x + f.y; f = unpack2(a01); ra.y = f.x + f.y;   \
      f = unpack2(a10); rb.x = f.x + f.y; f = unpack2(a11); rb.y = f.x + f.y;   \
      *(float2*)&red[G][0][w][l][0] = ra;                                       \
      *(float2*)&red[G][1][w][l][0] = rb; }                                     \
    __syncthreads();                                                            \
    float hv = 0.f;                                                             \
    if (tid < 128) {                                                            \
      const float* rf = &red[G][oj & 1][0][oj >> 1][obl];                       \
      float sum = rf[0] + rf[64] + rf[128] + rf[192]                            \
                + rf[256] + rf[320] + rf[384] + rf[448];                        \
      float pre = XP + sum + bh;                                                \
      float e = __expf(pre + pre);                                              \
      hv = 1.f - __fdividef(2.f, e + 1.f);                                      \
      float hvn = __shfl_down_sync(0xffffffffu, hv, 1);                         \
      if (((T) + 1 < SS) && !(oj & 1)) {                                        \
        ull v = packf2(hv, hvn);                                                \
        const uint32_t so = (uint32_t)(((G) * 2 + ((S) ^ 1)) * 4096);           \
        _Pragma("unroll")                                                       \
        for (int r = 0; r < CL; r++) st_cluster_b64(rh[r] + so, v);             \
      }                                                                         \
    }                                                                           \
    __syncthreads();                                                            \
    if (((T) + 1 < SS) && tid < 8)                                              \
      mbar_arrive_remote(rma + (uint32_t)(((G) * 2 + ((S) ^ 1)) * 8));          \
    if (tid < 128) {                                                            \
      __stcs(out + OB + (size_t)(T) * HH, hv);                                  \
      HL = hv;                                                                  \
      if ((T) + 1 < SS) XP = __ldcs(out + OB + (size_t)((T) + 1) * HH);         \
    }                                                                           \
  }

    for (int t = 0; t < SS; t += 2) {
        GSTEP(t,     0, 0, phA0, xpA, hlA, obA);
        GSTEP(t,     0, 1, phB0, xpB, hlB, obB);
        GSTEP(t + 1, 1, 0, phA1, xpA, hlA, obA);
        GSTEP(t + 1, 1, 1, phB1, xpB, hlB, obB);
    }
#undef GSTEP

    if (write_hfinal && tid < 128) {
        out[(size_t)BB * SS * HH + (size_t)(b0 + obl) * HH + gj] = hlA;
        out[(size_t)BB * SS * HH + (size_t)(b0 + 2 + obl) * HH + gj] = hlB;
    }
    asm volatile("barrier.cluster.arrive.aligned;" ::: "memory");
    asm volatile("barrier.cluster.wait.aligned;" ::: "memory");
}

// ---------------- launch ----------------
extern "C" void kernel_launch(void* const* d_in, const int* in_sizes, int n_in,
                              void* d_out, int out_size) {
    const float* inputs = (const float*)d_in[0];   // [64, 2048, 512]
    const float* h0     = (const float*)d_in[1];   // [64, 512]
    const float* W_ih   = (const float*)d_in[2];   // [512, 512]
    const float* W_hh   = (const float*)d_in[3];   // [512, 512]
    const float* b_ih   = (const float*)d_in[4];   // [512]
    const float* b_hh   = (const float*)d_in[5];   // [512]
    float* out = (float*)d_out;

    // Phase 1: x_proj into the outs region of d_out (scan overwrites in place)
    dim3 g1((BB * SS) / 128, HH / 128, 1);
    xproj_kernel<<<g1, 256>>>(inputs, W_ih, b_ih, out);

    // Phase 2: 16 clusters of 8 CTAs; register scatter + count-8 mbarriers
    long long need = (long long)BB * SS * HH + (long long)BB * HH;
    int wf = ((long long)out_size >= need) ? 1 : 0;
    rnn_scan_kernel<<<NCTA, 256>>>(h0, W_hh, b_hh, out, wf);
}

// round 12
// speedup vs baseline: 1.4884x; 1.3063x over previous
#include <cuda_runtime.h>
#include <cstdint>

// Problem constants
#define BB     64
#define SS     2048
#define INDIM  512
#define HH     512
#define CL     8            // cluster size (j-split of W_hh)
#define NCTA   128          // 16 clusters x 8 CTAs

// padded h block: kp index -> kp + (kp>>6)*2  (2 ull pad per 64 kp)
// block = 264 kp-slots x 2 batches = 528 ull = 4224 bytes per (grp,slot)
#define BLK_ULL   528
#define BLK_BYTES 4224

typedef unsigned long long ull;

// ---------------- packed f32x2 helpers (FFMA2 path, sm_103a) ----------------
__device__ __forceinline__ void ffma2(ull& acc, ull a, ull b) {
    asm volatile("fma.rn.f32x2 %0, %1, %2, %0;" : "+l"(acc) : "l"(a), "l"(b));
}
__device__ __forceinline__ ull pack2(float x) {
    ull r; asm("mov.b64 %0, {%1, %1};" : "=l"(r) : "f"(x)); return r;
}
__device__ __forceinline__ float2 unpack2(ull v) {
    float2 r; asm("mov.b64 {%0, %1}, %2;" : "=f"(r.x), "=f"(r.y) : "l"(v)); return r;
}
__device__ __forceinline__ uint32_t smem_u32(const void* p) {
    uint32_t a;
    asm("{ .reg .u64 t; cvta.to.shared.u64 t, %1; cvt.u32.u64 %0, t; }" : "=r"(a) : "l"(p));
    return a;
}
__device__ __forceinline__ uint32_t mapa_rank(uint32_t laddr, uint32_t rank) {
    uint32_t r;
    asm("mapa.shared::cluster.u32 %0, %1, %2;" : "=r"(r) : "r"(laddr), "r"(rank));
    return r;
}
__device__ __forceinline__ void mbar_inval(uint32_t mbar) {
    asm volatile("mbarrier.inval.shared.b64 [%0];" :: "r"(mbar) : "memory");
}
__device__ __forceinline__ void mbar_init(uint32_t mbar, uint32_t cnt) {
    asm volatile("mbarrier.init.shared.b64 [%0], %1;" :: "r"(mbar), "r"(cnt) : "memory");
}
__device__ __forceinline__ void mbar_arrive_expect_tx(uint32_t mbar, uint32_t tx) {
    asm volatile("mbarrier.arrive.expect_tx.shared.b64 _, [%0], %1;"
                 :: "r"(mbar), "r"(tx) : "memory");
}
__device__ __forceinline__ void mbar_wait_cluster(uint32_t mbar, uint32_t parity) {
    asm volatile(
        "{\n\t.reg .pred P;\n\t"
        "WL_%=:\n\t"
        "mbarrier.try_wait.parity.acquire.cluster.shared::cta.b64 P, [%0], %1, 0x989680;\n\t"
        "@!P bra WL_%=;\n\t}"
        :: "r"(mbar), "r"(parity) : "memory");
}
// bulk smem->remote smem copy, complete_tx on the remote rank's mbarrier
__device__ __forceinline__ void bulk_copy_cluster(uint32_t rdst, uint32_t lsrc,
                                                  uint32_t bytes, uint32_t rmbar) {
    asm volatile(
        "cp.async.bulk.shared::cluster.shared::cta.mbarrier::complete_tx::bytes "
        "[%0], [%1], %2, [%3];"
        :: "r"(rdst), "r"(lsrc), "r"(bytes), "r"(rmbar) : "memory");
}

// ---------------- Phase 1: x_proj = inputs @ W_ih^T + b_ih ----------------
__global__ __launch_bounds__(256) void xproj_kernel(
    const float* __restrict__ A, const float* __restrict__ W,
    const float* __restrict__ bias, float* __restrict__ C) {
    __shared__ float As[16][132];
    __shared__ float Bs[16][132];

    const int tid = threadIdx.x;
    const int m0 = blockIdx.x * 128;
    const int n0 = blockIdx.y * 128;
    const int lr = tid >> 2;
    const int lk = (tid & 3) << 2;
    const int tx = tid & 15;
    const int ty = tid >> 4;

    ull acc[8][4];
#pragma unroll
    for (int i = 0; i < 8; i++)
#pragma unroll
        for (int j = 0; j < 4; j++) acc[i][j] = 0ull;

    for (int k0 = 0; k0 < INDIM; k0 += 16) {
        float4 a0 = *(const float4*)(A + (size_t)(m0 + lr) * INDIM + k0 + lk);
        float4 a1 = *(const float4*)(A + (size_t)(m0 + lr + 64) * INDIM + k0 + lk);
        float4 w0 = *(const float4*)(W + (size_t)(n0 + lr) * INDIM + k0 + lk);
        float4 w1 = *(const float4*)(W + (size_t)(n0 + lr + 64) * INDIM + k0 + lk);
        __syncthreads();
        As[lk + 0][lr] = a0.x; As[lk + 1][lr] = a0.y; As[lk + 2][lr] = a0.z; As[lk + 3][lr] = a0.w;
        As[lk + 0][lr + 64] = a1.x; As[lk + 1][lr + 64] = a1.y; As[lk + 2][lr + 64] = a1.z; As[lk + 3][lr + 64] = a1.w;
        Bs[lk + 0][lr] = w0.x; Bs[lk + 1][lr] = w0.y; Bs[lk + 2][lr] = w0.z; Bs[lk + 3][lr] = w0.w;
        Bs[lk + 0][lr + 64] = w1.x; Bs[lk + 1][lr + 64] = w1.y; Bs[lk + 2][lr + 64] = w1.z; Bs[lk + 3][lr + 64] = w1.w;
        __syncthreads();
#pragma unroll
        for (int k = 0; k < 16; k++) {
            float4 am0 = *(const float4*)&As[k][ty * 4];
            float4 am1 = *(const float4*)&As[k][64 + ty * 4];
            ulonglong2 bn0 = *(const ulonglong2*)&Bs[k][tx * 4];
            ulonglong2 bn1 = *(const ulonglong2*)&Bs[k][64 + tx * 4];
            float am[8] = {am0.x, am0.y, am0.z, am0.w, am1.x, am1.y, am1.z, am1.w};
#pragma unroll
            for (int i = 0; i < 8; i++) {
                ull ap = pack2(am[i]);
                ffma2(acc[i][0], ap, bn0.x);
                ffma2(acc[i][1], ap, bn0.y);
                ffma2(acc[i][2], ap, bn1.x);
                ffma2(acc[i][3], ap, bn1.y);
            }
        }
    }

    float4 bA = *(const float4*)(bias + n0 + tx * 4);
    float4 bBv = *(const float4*)(bias + n0 + 64 + tx * 4);
#pragma unroll
    for (int i = 0; i < 8; i++) {
        int m = m0 + ((i < 4) ? (ty * 4 + i) : (64 + ty * 4 + (i - 4)));
        float2 c0 = unpack2(acc[i][0]);
        float2 c1 = unpack2(acc[i][1]);
        float2 c2 = unpack2(acc[i][2]);
        float2 c3 = unpack2(acc[i][3]);
        float4 o0 = make_float4(c0.x + bA.x, c0.y + bA.y, c1.x + bA.z, c1.y + bA.w);
        float4 o1 = make_float4(c2.x + bBv.x, c2.y + bBv.y, c3.x + bBv.z, c3.y + bBv.w);
        *(float4*)(C + (size_t)m * HH + n0 + tx * 4) = o0;
        *(float4*)(C + (size_t)m * HH + n0 + 64 + tx * 4) = o1;
    }
}

// ---------------- Phase 2: lean warp-reduce scan + bulk DSMEM exchange -----
// Cluster of 8 CTAs = 4 batches in 2 groups of 2. Rank r owns j in
// [64r,64r+64). Thread = (j, k-quarter): warp w covers j-block [8w,8w+8),
// lane = j(3b) + q(2b). W row-quarter in regs (64 ull). One broadcast
// LDS.128 per k-pair feeds BOTH batches; reduce = 2x shfl.xor per batch.
// Transport = R5's proven 8x512B bulk copies + expect_tx mbarriers.
__global__ __launch_bounds__(256, 1) __cluster_dims__(CL, 1, 1)
void rnn_scan_kernel(
    const float* __restrict__ h0, const float* __restrict__ W_hh,
    const float* __restrict__ b_hh, float* __restrict__ out, int write_hfinal) {
    __shared__ __align__(16) ull hsp[4][BLK_ULL];   // [(grp*2+slot)][padded kp*2+b]
    __shared__ __align__(16) ull stg[2][2][64];     // [grp][slot][jp*2+b]
    __shared__ ull mbars[4];                        // [grp*2 + slot]

    const int tid = threadIdx.x;
    const int w = tid >> 5;
    const int l = tid & 31;
    const int jl = l & 7;              // j within warp block
    const int q = l >> 3;              // k-quarter
    uint32_t rank;
    asm("mov.u32 %0, %%cluster_ctarank;" : "=r"(rank));
    const int j0 = (int)rank * 64;
    const int b0 = (blockIdx.x >> 3) * 4;
    const int myj = 8 * w + jl;        // local j in [0,64)
    const int gj = j0 + myj;

    // ---- W row-quarter into registers: 64 k-pairs of row gj, quarter q ----
    ull Wr[64];
    {
        const ull* wrow = (const ull*)(W_hh + (size_t)gj * HH) + q * 64;
#pragma unroll
        for (int p = 0; p < 64; p++) Wr[p] = wrow[p];
    }
    const float bh = b_hh[gj];

    // ---- init h slot 0 of both groups from h0 (padded layout) ----
#pragma unroll
    for (int g = 0; g < 2; g++) {
        float* hf = (float*)&hsp[g * 2][0];
        for (int i = tid; i < 2 * HH; i += 256) {
            int b = i >> 9, k = i & 511, kp = k >> 1;
            hf[(kp + (kp >> 6) * 2) * 4 + b * 2 + (k & 1)] =
                h0[(size_t)(b0 + 2 * g + b) * HH + k];
        }
    }

    const uint32_t mb_local = smem_u32(&mbars[0]);
    if (tid == 0) {
#pragma unroll
        for (int i = 0; i < 4; i++) {
            mbar_inval(mb_local + 8 * i);
            mbar_init(mb_local + 8 * i, 1);
            mbar_arrive_expect_tx(mb_local + 8 * i, 4096u);
        }
        asm volatile("fence.mbarrier_init.release.cluster;" ::: "memory");
    }
    __syncthreads();
    asm volatile("barrier.cluster.arrive.aligned;" ::: "memory");
    asm volatile("barrier.cluster.wait.aligned;" ::: "memory");

    // remote bases; my 512B slice lands at padded offset 512r + 32*(r>>1)
    const uint32_t hbase = smem_u32(&hsp[0][0]);
    const uint32_t sbase = smem_u32(&stg[0][0][0]);
    const uint32_t my_off = 512u * rank + 32u * (rank >> 1);
    uint32_t rh[CL], rm[CL];
#pragma unroll
    for (int r = 0; r < CL; r++) {
        rh[r] = mapa_rank(hbase, (uint32_t)r);
        rm[r] = mapa_rank(mb_local, (uint32_t)r);
    }

    // consumer read base for this lane's quarter: ull index 132q (+2i per kp)
    const ull* hq = &hsp[0][0] + 132 * q;

    // output streams (q==0 lanes finalize both batches of each group)
    const size_t obA0 = (size_t)(b0 + 0) * SS * HH + gj;
    const size_t obA1 = (size_t)(b0 + 1) * SS * HH + gj;
    const size_t obB0 = (size_t)(b0 + 2) * SS * HH + gj;
    const size_t obB1 = (size_t)(b0 + 3) * SS * HH + gj;
    float xpA0 = 0.f, xpA1 = 0.f, xpB0 = 0.f, xpB1 = 0.f;
    float hlA0 = 0.f, hlA1 = 0.f, hlB0 = 0.f, hlB1 = 0.f;
    if (q == 0) {
        xpA0 = __ldcs(out + obA0); xpA1 = __ldcs(out + obA1);
        xpB0 = __ldcs(out + obB0); xpB1 = __ldcs(out + obB1);
    }
    uint32_t phA0 = 0, phA1 = 0, phB0 = 0, phB1 = 0;

#define GSTEP(T, S, G, PH, XP0, XP1, HL0, HL1, OB0, OB1)                        \
  {                                                                             \
    if ((T) > 0) {                                                              \
      mbar_wait_cluster(mb_local + ((G) * 2 + (S)) * 8, PH);                    \
      PH ^= 1u;                                                                 \
      if (tid == 0) mbar_arrive_expect_tx(mb_local + ((G) * 2 + (S)) * 8, 4096u);\
    }                                                                           \
    const ull* hb = hq + ((G) * 2 + (S)) * BLK_ULL;                             \
    ull a0 = 0, a1 = 0;                                                         \
    _Pragma("unroll")                                                           \
    for (int p = 0; p < 64; p++) {                                              \
      ulonglong2 hx = *(const ulonglong2*)(hb + 2 * p);                         \
      ffma2(a0, hx.x, Wr[p]);                                                   \
      ffma2(a1, hx.y, Wr[p]);                                                   \
    }                                                                           \
    float2 f0 = unpack2(a0), f1 = unpack2(a1);                                  \
    float s0 = f0.x + f0.y, s1 = f1.x + f1.y;                                   \
    s0 += __shfl_xor_sync(0xffffffffu, s0, 8);                                  \
    s1 += __shfl_xor_sync(0xffffffffu, s1, 8);                                  \
    s0 += __shfl_xor_sync(0xffffffffu, s0, 16);                                 \
    s1 += __shfl_xor_sync(0xffffffffu, s1, 16);                                 \
    float hv0 = 0.f, hv1 = 0.f;                                                 \
    if (q == 0) {                                                               \
      float p0 = XP0 + s0 + bh, p1 = XP1 + s1 + bh;                             \
      float e0 = __expf(p0 + p0), e1 = __expf(p1 + p1);                         \
      hv0 = 1.f - __fdividef(2.f, e0 + 1.f);                                    \
      hv1 = 1.f - __fdividef(2.f, e1 + 1.f);                                    \
      float* sf = (float*)&stg[G][S][0];                                        \
      sf[(myj >> 1) * 4 + 0 + (myj & 1)] = hv0;                                 \
      sf[(myj >> 1) * 4 + 2 + (myj & 1)] = hv1;                                 \
    }                                                                           \
    __syncthreads();                                                            \
    if (((T) + 1 < SS) && tid < CL) {                                           \
      asm volatile("fence.proxy.async.shared::cta;" ::: "memory");              \
      bulk_copy_cluster(                                                        \
          rh[tid] + (uint32_t)(((G) * 2 + ((S) ^ 1)) * BLK_BYTES) + my_off,     \
          sbase + (uint32_t)(((G) * 2 + (S)) * 512), 512u,                      \
          rm[tid] + (uint32_t)(((G) * 2 + ((S) ^ 1)) * 8));                     \
    }                                                                           \
    if (q == 0) {                                                               \
      __stcs(out + OB0 + (size_t)(T) * HH, hv0);                                \
      __stcs(out + OB1 + (size_t)(T) * HH, hv1);                                \
      HL0 = hv0; HL1 = hv1;                                                     \
      if ((T) + 1 < SS) {                                                       \
        XP0 = __ldcs(out + OB0 + (size_t)((T) + 1) * HH);                       \
        XP1 = __ldcs(out + OB1 + (size_t)((T) + 1) * HH);                       \
      }                                                                         \
    }                                                                           \
  }

    for (int t = 0; t < SS; t += 2) {
        GSTEP(t,     0, 0, phA0, xpA0, xpA1, hlA0, hlA1, obA0, obA1);
        GSTEP(t,     0, 1, phB0, xpB0, xpB1, hlB0, hlB1, obB0, obB1);
        GSTEP(t + 1, 1, 0, phA1, xpA0, xpA1, hlA0, hlA1, obA0, obA1);
        GSTEP(t + 1, 1, 1, phB1, xpB0, xpB1, hlB0, hlB1, obB0, obB1);
    }
#undef GSTEP

    if (write_hfinal && q == 0) {
        const size_t hb0 = (size_t)BB * SS * HH;
        out[hb0 + (size_t)(b0 + 0) * HH + gj] = hlA0;
        out[hb0 + (size_t)(b0 + 1) * HH + gj] = hlA1;
        out[hb0 + (size_t)(b0 + 2) * HH + gj] = hlB0;
        out[hb0 + (size_t)(b0 + 3) * HH + gj] = hlB1;
    }
    asm volatile("barrier.cluster.arrive.aligned;" ::: "memory");
    asm volatile("barrier.cluster.wait.aligned;" ::: "memory");
}

// ---------------- launch ----------------
extern "C" void kernel_launch(void* const* d_in, const int* in_sizes, int n_in,
                              void* d_out, int out_size) {
    const float* inputs = (const float*)d_in[0];   // [64, 2048, 512]
    const float* h0     = (const float*)d_in[1];   // [64, 512]
    const float* W_ih   = (const float*)d_in[2];   // [512, 512]
    const float* W_hh   = (const float*)d_in[3];   // [512, 512]
    const float* b_ih   = (const float*)d_in[4];   // [512]
    const float* b_hh   = (const float*)d_in[5];   // [512]
    float* out = (float*)d_out;

    // Phase 1: x_proj into the outs region of d_out (scan overwrites in place)
    dim3 g1((BB * SS) / 128, HH / 128, 1);
    xproj_kernel<<<g1, 256>>>(inputs, W_ih, b_ih, out);

    // Phase 2: lean warp-reduce scan, bulk-DSMEM transport (R5 lineage)
    long long need = (long long)BB * SS * HH + (long long)BB * HH;
    int wf = ((long long)out_size >= need) ? 1 : 0;
    rnn_scan_kernel<<<NCTA, 256>>>(h0, W_hh, b_hh, out, wf);
}

// round 14
// speedup vs baseline: 1.5117x; 1.0156x over previous
#include <cuda_runtime.h>
#include <cstdint>

// Problem constants
#define BB     64
#define SS     2048
#define INDIM  512
#define HH     512
#define CL     8            // cluster size (j-split of W_hh)
#define NCTA   128          // 16 clusters x 8 CTAs

typedef unsigned long long ull;

// ---------------- packed f32x2 helpers (FFMA2 path, sm_103a) ----------------
__device__ __forceinline__ void ffma2(ull& acc, ull a, ull b) {
    asm volatile("fma.rn.f32x2 %0, %1, %2, %0;" : "+l"(acc) : "l"(a), "l"(b));
}
__device__ __forceinline__ ull pack2(float x) {
    ull r; asm("mov.b64 %0, {%1, %1};" : "=l"(r) : "f"(x)); return r;
}
__device__ __forceinline__ float2 unpack2(ull v) {
    float2 r; asm("mov.b64 {%0, %1}, %2;" : "=f"(r.x), "=f"(r.y) : "l"(v)); return r;
}
__device__ __forceinline__ uint32_t smem_u32(const void* p) {
    uint32_t a;
    asm("{ .reg .u64 t; cvta.to.shared.u64 t, %1; cvt.u32.u64 %0, t; }" : "=r"(a) : "l"(p));
    return a;
}
__device__ __forceinline__ uint32_t mapa_rank(uint32_t laddr, uint32_t rank) {
    uint32_t r;
    asm("mapa.shared::cluster.u32 %0, %1, %2;" : "=r"(r) : "r"(laddr), "r"(rank));
    return r;
}
__device__ __forceinline__ void mbar_init(uint32_t mbar, uint32_t cnt) {
    asm volatile("mbarrier.init.shared.b64 [%0], %1;" :: "r"(mbar), "r"(cnt) : "memory");
}
__device__ __forceinline__ void mbar_arrive_expect_tx(uint32_t mbar, uint32_t tx) {
    asm volatile("mbarrier.arrive.expect_tx.shared.b64 _, [%0], %1;"
                 :: "r"(mbar), "r"(tx) : "memory");
}
__device__ __forceinline__ void mbar_wait_cluster(uint32_t mbar, uint32_t parity) {
    asm volatile(
        "{\n\t.reg .pred P;\n\t"
        "WL_%=:\n\t"
        "mbarrier.try_wait.parity.acquire.cluster.shared::cta.b64 P, [%0], %1, 0x989680;\n\t"
        "@!P bra WL_%=;\n\t}"
        :: "r"(mbar), "r"(parity) : "memory");
}
// bulk smem->remote smem copy, complete_tx on the remote rank's mbarrier
__device__ __forceinline__ void bulk_copy_cluster(uint32_t rdst, uint32_t lsrc,
                                                  uint32_t bytes, uint32_t rmbar) {
    asm volatile(
        "cp.async.bulk.shared::cluster.shared::cta.mbarrier::complete_tx::bytes "
        "[%0], [%1], %2, [%3];"
        :: "r"(rdst), "r"(lsrc), "r"(bytes), "r"(rmbar) : "memory");
}
__device__ __forceinline__ void fence_pa() {
    asm volatile("fence.proxy.async.shared::cta;" ::: "memory");
}

// ---------------- Phase 1: x_proj = inputs @ W_ih^T + b_ih ----------------
__global__ __launch_bounds__(256) void xproj_kernel(
    const float* __restrict__ A, const float* __restrict__ W,
    const float* __restrict__ bias, float* __restrict__ C) {
    __shared__ float As[16][132];
    __shared__ float Bs[16][132];

    const int tid = threadIdx.x;
    const int m0 = blockIdx.x * 128;
    const int n0 = blockIdx.y * 128;
    const int lr = tid >> 2;
    const int lk = (tid & 3) << 2;
    const int tx = tid & 15;
    const int ty = tid >> 4;

    ull acc[8][4];
#pragma unroll
    for (int i = 0; i < 8; i++)
#pragma unroll
        for (int j = 0; j < 4; j++) acc[i][j] = 0ull;

    for (int k0 = 0; k0 < INDIM; k0 += 16) {
        float4 a0 = *(const float4*)(A + (size_t)(m0 + lr) * INDIM + k0 + lk);
        float4 a1 = *(const float4*)(A + (size_t)(m0 + lr + 64) * INDIM + k0 + lk);
        float4 w0 = *(const float4*)(W + (size_t)(n0 + lr) * INDIM + k0 + lk);
        float4 w1 = *(const float4*)(W + (size_t)(n0 + lr + 64) * INDIM + k0 + lk);
        __syncthreads();
        As[lk + 0][lr] = a0.x; As[lk + 1][lr] = a0.y; As[lk + 2][lr] = a0.z; As[lk + 3][lr] = a0.w;
        As[lk + 0][lr + 64] = a1.x; As[lk + 1][lr + 64] = a1.y; As[lk + 2][lr + 64] = a1.z; As[lk + 3][lr + 64] = a1.w;
        Bs[lk + 0][lr] = w0.x; Bs[lk + 1][lr] = w0.y; Bs[lk + 2][lr] = w0.z; Bs[lk + 3][lr] = w0.w;
        Bs[lk + 0][lr + 64] = w1.x; Bs[lk + 1][lr + 64] = w1.y; Bs[lk + 2][lr + 64] = w1.z; Bs[lk + 3][lr + 64] = w1.w;
        __syncthreads();
#pragma unroll
        for (int k = 0; k < 16; k++) {
            float4 am0 = *(const float4*)&As[k][ty * 4];
            float4 am1 = *(const float4*)&As[k][64 + ty * 4];
            ulonglong2 bn0 = *(const ulonglong2*)&Bs[k][tx * 4];
            ulonglong2 bn1 = *(const ulonglong2*)&Bs[k][64 + tx * 4];
            float am[8] = {am0.x, am0.y, am0.z, am0.w, am1.x, am1.y, am1.z, am1.w};
#pragma unroll
            for (int i = 0; i < 8; i++) {
                ull ap = pack2(am[i]);
                ffma2(acc[i][0], ap, bn0.x);
                ffma2(acc[i][1], ap, bn0.y);
                ffma2(acc[i][2], ap, bn1.x);
                ffma2(acc[i][3], ap, bn1.y);
            }
        }
    }

    float4 bA = *(const float4*)(bias + n0 + tx * 4);
    float4 bBv = *(const float4*)(bias + n0 + 64 + tx * 4);
#pragma unroll
    for (int i = 0; i < 8; i++) {
        int m = m0 + ((i < 4) ? (ty * 4 + i) : (64 + ty * 4 + (i - 4)));
        float2 c0 = unpack2(acc[i][0]);
        float2 c1 = unpack2(acc[i][1]);
        float2 c2 = unpack2(acc[i][2]);
        float2 c3 = unpack2(acc[i][3]);
        float4 o0 = make_float4(c0.x + bA.x, c0.y + bA.y, c1.x + bA.z, c1.y + bA.w);
        float4 o1 = make_float4(c2.x + bBv.x, c2.y + bBv.y, c3.x + bBv.z, c3.y + bBv.w);
        *(float4*)(C + (size_t)m * HH + n0 + tx * 4) = o0;
        *(float4*)(C + (size_t)m * HH + n0 + 64 + tx * 4) = o1;
    }
}

// ---------------- Phase 2: scan — butterfly all-gather exchange ------------
// Cluster of 8 CTAs = 4 batches in 2 groups of 2. Rank r owns j in
// [64r,64r+64); W in registers (R5 compute core). Exchange per (grp,slot):
// recursive doubling — r1: own 512B -> rank^1; r2 (after r1 in): pair 1KB ->
// rank^2; r3 (after r2 in): quad 2KB -> rank^4. ONE engine copy per CTA per
// round (vs 8 serialized). m1/m2/m3 mbarriers per (grp,slot); tid0 forwards
// between GSTEPs; consumers wait all three.
#define MBOFF(G, S, R) ((uint32_t)((((G) * 2 + (S)) * 3 + (R)) * 8))
#define BLK(G, S)      ((uint32_t)(((G) * 2 + (S)) * 4096))

__global__ __launch_bounds__(256, 1) __cluster_dims__(CL, 1, 1)
void rnn_scan_kernel(
    const float* __restrict__ h0, const float* __restrict__ W_hh,
    const float* __restrict__ b_hh, float* __restrict__ out, int write_hfinal) {
    __shared__ __align__(16) ull   hsp[2][2][256][2];   // [grp][slot][kpair][b] 16KB
    __shared__ float red[2][2][8][32][2];               // [grp][jpar][w][jp][b] 8KB
    __shared__ ull   mbars[12];                         // [(grp*2+slot)*3 + round]

    const int tid = threadIdx.x;
    const int w = tid >> 5;
    const int l = tid & 31;
    uint32_t rank;
    asm("mov.u32 %0, %%cluster_ctarank;" : "=r"(rank));
    const int j0 = (int)rank * 64;
    const int b0 = (blockIdx.x >> 3) * 4;
    const int obl = (tid >> 6) & 1;
    const int oj = tid & 63;
    const int gj = j0 + oj;

    // ---- W slice into registers, k-paired ----
    ull Wp0[32], Wp1[32];
    {
        const ull* w0p = (const ull*)(W_hh + (size_t)(j0 + 2 * l) * HH + w * 64);
        const ull* w1p = (const ull*)(W_hh + (size_t)(j0 + 2 * l + 1) * HH + w * 64);
#pragma unroll
        for (int p = 0; p < 32; p++) { Wp0[p] = w0p[p]; Wp1[p] = w1p[p]; }
    }
    const float bh = b_hh[gj];

    // ---- init h slot 0 of both groups from h0 ----
#pragma unroll
    for (int g = 0; g < 2; g++) {
        float* hf = (float*)&hsp[g][0][0][0];
        for (int i = tid; i < 2 * HH; i += 256) {
            int b = i >> 9, k = i & 511;
            hf[(k >> 1) * 4 + b * 2 + (k & 1)] = h0[(size_t)(b0 + 2 * g + b) * HH + k];
        }
    }

    const uint32_t mb_local = smem_u32(&mbars[0]);
    if (tid == 0) {
#pragma unroll
        for (int i = 0; i < 12; i++) {
            uint32_t tx = (i % 3 == 0) ? 512u : ((i % 3 == 1) ? 1024u : 2048u);
            mbar_init(mb_local + 8 * i, 1);
            mbar_arrive_expect_tx(mb_local + 8 * i, tx);
        }
        asm volatile("fence.mbarrier_init.release.cluster;" ::: "memory");
    }
    __syncthreads();
    asm volatile("barrier.cluster.arrive.aligned;" ::: "memory");
    asm volatile("barrier.cluster.wait.aligned;" ::: "memory");

    // butterfly peer addresses
    const uint32_t hbase = smem_u32(&hsp[0][0][0][0]);
    const uint32_t hR1 = mapa_rank(hbase, rank ^ 1), mR1 = mapa_rank(mb_local, rank ^ 1);
    const uint32_t hR2 = mapa_rank(hbase, rank ^ 2), mR2 = mapa_rank(mb_local, rank ^ 2);
    const uint32_t hR4 = mapa_rank(hbase, rank ^ 4), mR4 = mapa_rank(mb_local, rank ^ 4);
    const uint32_t off_self = rank * 512u;
    const uint32_t off_pair = (rank & ~1u) * 512u;
    const uint32_t off_quad = (rank & ~3u) * 512u;
    // staging index of this thread's hv inside the own 512B slice (floats)
    const int sidx = (oj >> 1) * 4 + obl * 2 + (oj & 1);

    const size_t obA = (size_t)(b0 + obl) * SS * HH + gj;
    const size_t obB = (size_t)(b0 + 2 + obl) * SS * HH + gj;
    float xpA = 0.f, xpB = 0.f, hlA = 0.f, hlB = 0.f;
    if (tid < 128) { xpA = __ldcs(out + obA); xpB = __ldcs(out + obB); }
    uint32_t phA0 = 0, phA1 = 0, phB0 = 0, phB1 = 0;

#define GSTEP(T, S, G, PH, XP, HL, OB)                                          \
  {                                                                             \
    if ((T) > 0) {                                                              \
      mbar_wait_cluster(mb_local + MBOFF(G, S, 0), PH);                         \
      mbar_wait_cluster(mb_local + MBOFF(G, S, 1), PH);                         \
      mbar_wait_cluster(mb_local + MBOFF(G, S, 2), PH);                         \
      PH ^= 1u;                                                                 \
      if (tid == 0) {                                                           \
        mbar_arrive_expect_tx(mb_local + MBOFF(G, S, 0), 512u);                 \
        mbar_arrive_expect_tx(mb_local + MBOFF(G, S, 1), 1024u);                \
        mbar_arrive_expect_tx(mb_local + MBOFF(G, S, 2), 2048u);                \
      }                                                                         \
    }                                                                           \
    const ull* hb = &hsp[G][S][w * 32][0];                                      \
    ull a00 = 0, a01 = 0, a10 = 0, a11 = 0;                                     \
    _Pragma("unroll")                                                           \
    for (int p = 0; p < 32; p++) {                                              \
      ulonglong2 hx = *(const ulonglong2*)(hb + p * 2);                         \
      ull w0 = Wp0[p], w1 = Wp1[p];                                             \
      ffma2(a00, hx.x, w0); ffma2(a01, hx.y, w0);                               \
      ffma2(a10, hx.x, w1); ffma2(a11, hx.y, w1);                               \
    }                                                                           \
    { float2 f; float2 ra, rb;                                                  \
      f = unpack2(a00); ra.x = f.x + f.y; f = unpack2(a01); ra.y = f.x + f.y;   \
      f = unpack2(a10); rb.x = f.x + f.y; f = unpack2(a11); rb.y = f.x + f.y;   \
      *(float2*)&red[G][0][w][l][0] = ra;                                       \
      *(float2*)&red[G][1][w][l][0] = rb; }                                     \
    __syncthreads();                                                            \
    float hv = 0.f;                                                             \
    if (tid < 128) {                                                            \
      const float* rf = &red[G][oj & 1][0][oj >> 1][obl];                       \
      float sum = rf[0] + rf[64] + rf[128] + rf[192]                            \
                + rf[256] + rf[320] + rf[384] + rf[448];                        \
      float pre = XP + sum + bh;                                                \
      float e = __expf(pre + pre);                                              \
      hv = 1.f - __fdividef(2.f, e + 1.f);                                      \
      if ((T) + 1 < SS)                                                         \
        ((float*)&hsp[0][0][0][0])[(BLK(G, (S) ^ 1) + off_self) / 4 + sidx] = hv;\
    }                                                                           \
    __syncthreads();                                                            \
    if (((T) + 1 < SS) && tid == 0) {                                           \
      fence_pa();                                                               \
      bulk_copy_cluster(hR1 + BLK(G, (S) ^ 1) + off_self,                       \
                        hbase + BLK(G, (S) ^ 1) + off_self, 512u,               \
                        mR1 + MBOFF(G, (S) ^ 1, 0));                            \
    }                                                                           \
    if (tid < 128) {                                                            \
      __stcs(out + OB + (size_t)(T) * HH, hv);                                  \
      HL = hv;                                                                  \
      if ((T) + 1 < SS) XP = __ldcs(out + OB + (size_t)((T) + 1) * HH);         \
    }                                                                           \
  }

// forwarding rounds for the exchange created at timestep T (slot SP = target):
// tid0 only — overlapped with other warps' progress into the next GSTEP waits.
#define FWD(T, SP, PH0, PH1)                                                    \
  if (((T) + 1 < SS) && tid == 0) {                                             \
    mbar_wait_cluster(mb_local + MBOFF(0, SP, 0), PH0);                         \
    fence_pa();                                                                 \
    bulk_copy_cluster(hR2 + BLK(0, SP) + off_pair,                              \
                      hbase + BLK(0, SP) + off_pair, 1024u,                     \
                      mR2 + MBOFF(0, SP, 1));                                   \
    mbar_wait_cluster(mb_local + MBOFF(1, SP, 0), PH1);                         \
    fence_pa();                                                                 \
    bulk_copy_cluster(hR2 + BLK(1, SP) + off_pair,                              \
                      hbase + BLK(1, SP) + off_pair, 1024u,                     \
                      mR2 + MBOFF(1, SP, 1));                                   \
    mbar_wait_cluster(mb_local + MBOFF(0, SP, 1), PH0);                         \
    fence_pa();                                                                 \
    bulk_copy_cluster(hR4 + BLK(0, SP) + off_quad,                              \
                      hbase + BLK(0, SP) + off_quad, 2048u,                     \
                      mR4 + MBOFF(0, SP, 2));                                   \
    mbar_wait_cluster(mb_local + MBOFF(1, SP, 1), PH1);                         \
    fence_pa();                                                                 \
    bulk_copy_cluster(hR4 + BLK(1, SP) + off_quad,                              \
                      hbase + BLK(1, SP) + off_quad, 2048u,                     \
                      mR4 + MBOFF(1, SP, 2));                                   \
  }

    for (int t = 0; t < SS; t += 2) {
        GSTEP(t,     0, 0, phA0, xpA, hlA, obA);
        GSTEP(t,     0, 1, phB0, xpB, hlB, obB);
        FWD(t, 1, phA1, phB1);
        GSTEP(t + 1, 1, 0, phA1, xpA, hlA, obA);
        GSTEP(t + 1, 1, 1, phB1, xpB, hlB, obB);
        FWD(t + 1, 0, phA0, phB0);
    }
#undef GSTEP
#undef FWD

    if (write_hfinal && tid < 128) {
        out[(size_t)BB * SS * HH + (size_t)(b0 + obl) * HH + gj] = hlA;
        out[(size_t)BB * SS * HH + (size_t)(b0 + 2 + obl) * HH + gj] = hlB;
    }
    asm volatile("barrier.cluster.arrive.aligned;" ::: "memory");
    asm volatile("barrier.cluster.wait.aligned;" ::: "memory");
}

// ---------------- launch ----------------
extern "C" void kernel_launch(void* const* d_in, const int* in_sizes, int n_in,
                              void* d_out, int out_size) {
    const float* inputs = (const float*)d_in[0];   // [64, 2048, 512]
    const float* h0     = (const float*)d_in[1];   // [64, 512]
    const float* W_ih   = (const float*)d_in[2];   // [512, 512]
    const float* W_hh   = (const float*)d_in[3];   // [512, 512]
    const float* b_ih   = (const float*)d_in[4];   // [512]
    const float* b_hh   = (const float*)d_in[5];   // [512]
    float* out = (float*)d_out;

    // Phase 1: x_proj into the outs region of d_out (scan overwrites in place)
    dim3 g1((BB * SS) / 128, HH / 128, 1);
    xproj_kernel<<<g1, 256>>>(inputs, W_ih, b_ih, out);

    // Phase 2: 16 clusters of 8 CTAs; butterfly all-gather scan
    long long need = (long long)BB * SS * HH + (long long)BB * HH;
    int wf = ((long long)out_size >= need) ? 1 : 0;
    rnn_scan_kernel<<<NCTA, 256>>>(h0, W_hh, b_hh, out, wf);
}

// round 15
// speedup vs baseline: 1.6360x; 1.0822x over previous
#include <cuda_runtime.h>
#include <cstdint>

// Problem constants
#define BB     64
#define SS     2048
#define INDIM  512
#define HH     512
#define CL     8            // cluster size (j-split of W_hh)
#define NCTA   128          // 16 clusters x 8 CTAs

typedef unsigned long long ull;

// ---------------- packed f32x2 helpers (FFMA2 path, sm_103a) ----------------
__device__ __forceinline__ void ffma2(ull& acc, ull a, ull b) {
    asm volatile("fma.rn.f32x2 %0, %1, %2, %0;" : "+l"(acc) : "l"(a), "l"(b));
}
__device__ __forceinline__ ull pack2(float x) {
    ull r; asm("mov.b64 %0, {%1, %1};" : "=l"(r) : "f"(x)); return r;
}
__device__ __forceinline__ float2 unpack2(ull v) {
    float2 r; asm("mov.b64 {%0, %1}, %2;" : "=f"(r.x), "=f"(r.y) : "l"(v)); return r;
}
__device__ __forceinline__ uint32_t smem_u32(const void* p) {
    uint32_t a;
    asm("{ .reg .u64 t; cvta.to.shared.u64 t, %1; cvt.u32.u64 %0, t; }" : "=r"(a) : "l"(p));
    return a;
}
__device__ __forceinline__ uint32_t mapa_rank(uint32_t laddr, uint32_t rank) {
    uint32_t r;
    asm("mapa.shared::cluster.u32 %0, %1, %2;" : "=r"(r) : "r"(laddr), "r"(rank));
    return r;
}
__device__ __forceinline__ void mbar_init(uint32_t mbar, uint32_t cnt) {
    asm volatile("mbarrier.init.shared.b64 [%0], %1;" :: "r"(mbar), "r"(cnt) : "memory");
}
__device__ __forceinline__ void mbar_arrive_expect_tx(uint32_t mbar, uint32_t tx) {
    asm volatile("mbarrier.arrive.expect_tx.shared.b64 _, [%0], %1;"
                 :: "r"(mbar), "r"(tx) : "memory");
}
__device__ __forceinline__ void mbar_wait_cluster(uint32_t mbar, uint32_t parity) {
    asm volatile(
        "{\n\t.reg .pred P;\n\t"
        "WL_%=:\n\t"
        "mbarrier.try_wait.parity.acquire.cluster.shared::cta.b64 P, [%0], %1, 0x989680;\n\t"
        "@!P bra WL_%=;\n\t}"
        :: "r"(mbar), "r"(parity) : "memory");
}
// bulk smem->remote smem copy, complete_tx on the remote rank's mbarrier
__device__ __forceinline__ void bulk_copy_cluster(uint32_t rdst, uint32_t lsrc,
                                                  uint32_t bytes, uint32_t rmbar) {
    asm volatile(
        "cp.async.bulk.shared::cluster.shared::cta.mbarrier::complete_tx::bytes "
        "[%0], [%1], %2, [%3];"
        :: "r"(rdst), "r"(lsrc), "r"(bytes), "r"(rmbar) : "memory");
}
__device__ __forceinline__ void fence_pa() {
    asm volatile("fence.proxy.async.shared::cta;" ::: "memory");
}

// ---------------- Phase 1: x_proj = inputs @ W_ih^T + b_ih ----------------
__global__ __launch_bounds__(256) void xproj_kernel(
    const float* __restrict__ A, const float* __restrict__ W,
    const float* __restrict__ bias, float* __restrict__ C) {
    __shared__ float As[16][132];
    __shared__ float Bs[16][132];

    const int tid = threadIdx.x;
    const int m0 = blockIdx.x * 128;
    const int n0 = blockIdx.y * 128;
    const int lr = tid >> 2;
    const int lk = (tid & 3) << 2;
    const int tx = tid & 15;
    const int ty = tid >> 4;

    ull acc[8][4];
#pragma unroll
    for (int i = 0; i < 8; i++)
#pragma unroll
        for (int j = 0; j < 4; j++) acc[i][j] = 0ull;

    for (int k0 = 0; k0 < INDIM; k0 += 16) {
        float4 a0 = *(const float4*)(A + (size_t)(m0 + lr) * INDIM + k0 + lk);
        float4 a1 = *(const float4*)(A + (size_t)(m0 + lr + 64) * INDIM + k0 + lk);
        float4 w0 = *(const float4*)(W + (size_t)(n0 + lr) * INDIM + k0 + lk);
        float4 w1 = *(const float4*)(W + (size_t)(n0 + lr + 64) * INDIM + k0 + lk);
        __syncthreads();
        As[lk + 0][lr] = a0.x; As[lk + 1][lr] = a0.y; As[lk + 2][lr] = a0.z; As[lk + 3][lr] = a0.w;
        As[lk + 0][lr + 64] = a1.x; As[lk + 1][lr + 64] = a1.y; As[lk + 2][lr + 64] = a1.z; As[lk + 3][lr + 64] = a1.w;
        Bs[lk + 0][lr] = w0.x; Bs[lk + 1][lr] = w0.y; Bs[lk + 2][lr] = w0.z; Bs[lk + 3][lr] = w0.w;
        Bs[lk + 0][lr + 64] = w1.x; Bs[lk + 1][lr + 64] = w1.y; Bs[lk + 2][lr + 64] = w1.z; Bs[lk + 3][lr + 64] = w1.w;
        __syncthreads();
#pragma unroll
        for (int k = 0; k < 16; k++) {
            float4 am0 = *(const float4*)&As[k][ty * 4];
            float4 am1 = *(const float4*)&As[k][64 + ty * 4];
            ulonglong2 bn0 = *(const ulonglong2*)&Bs[k][tx * 4];
            ulonglong2 bn1 = *(const ulonglong2*)&Bs[k][64 + tx * 4];
            float am[8] = {am0.x, am0.y, am0.z, am0.w, am1.x, am1.y, am1.z, am1.w};
#pragma unroll
            for (int i = 0; i < 8; i++) {
                ull ap = pack2(am[i]);
                ffma2(acc[i][0], ap, bn0.x);
                ffma2(acc[i][1], ap, bn0.y);
                ffma2(acc[i][2], ap, bn1.x);
                ffma2(acc[i][3], ap, bn1.y);
            }
        }
    }

    float4 bA = *(const float4*)(bias + n0 + tx * 4);
    float4 bBv = *(const float4*)(bias + n0 + 64 + tx * 4);
#pragma unroll
    for (int i = 0; i < 8; i++) {
        int m = m0 + ((i < 4) ? (ty * 4 + i) : (64 + ty * 4 + (i - 4)));
        float2 c0 = unpack2(acc[i][0]);
        float2 c1 = unpack2(acc[i][1]);
        float2 c2 = unpack2(acc[i][2]);
        float2 c3 = unpack2(acc[i][3]);
        float4 o0 = make_float4(c0.x + bA.x, c0.y + bA.y, c1.x + bA.z, c1.y + bA.w);
        float4 o1 = make_float4(c2.x + bBv.x, c2.y + bBv.y, c3.x + bBv.z, c3.y + bBv.w);
        *(float4*)(C + (size_t)m * HH + n0 + tx * 4) = o0;
        *(float4*)(C + (size_t)m * HH + n0 + 64 + tx * 4) = o1;
    }
}

// ---------------- Phase 2: scan — radix-4+2 all-gather exchange ------------
// Cluster of 8 CTAs = 4 batches in 2 groups of 2; R5 compute core unchanged.
// Exchange per (grp,slot): hop1 = 3 parallel 512B copies to quad peers
// (r^1,r^2,r^3), mbarQ expect 1536; hop2 (FWD, after quad complete) = ONE
// 2KB copy of the quad block to the mirror r^4, mbarO expect 2048.
// Consumers wait mbarQ & mbarO. Tree chosen from measured l~1400, s~400:
// F = max(l+2s, C_other) + l  <<  l+7s (R5) and 3l (R14).
#define MBOFF(G, S, R) ((uint32_t)((((G) * 2 + (S)) * 2 + (R)) * 8))
#define BLK(G, S)      ((uint32_t)(((G) * 2 + (S)) * 4096))

__global__ __launch_bounds__(256, 1) __cluster_dims__(CL, 1, 1)
void rnn_scan_kernel(
    const float* __restrict__ h0, const float* __restrict__ W_hh,
    const float* __restrict__ b_hh, float* __restrict__ out, int write_hfinal) {
    __shared__ __align__(16) ull   hsp[2][2][256][2];   // [grp][slot][kpair][b] 16KB
    __shared__ float red[2][2][8][32][2];               // [grp][jpar][w][jp][b] 8KB
    __shared__ ull   mbars[8];                          // [(grp*2+slot)*2 + {Q,O}]

    const int tid = threadIdx.x;
    const int w = tid >> 5;
    const int l = tid & 31;
    uint32_t rank;
    asm("mov.u32 %0, %%cluster_ctarank;" : "=r"(rank));
    const int j0 = (int)rank * 64;
    const int b0 = (blockIdx.x >> 3) * 4;
    const int obl = (tid >> 6) & 1;
    const int oj = tid & 63;
    const int gj = j0 + oj;

    // ---- W slice into registers, k-paired ----
    ull Wp0[32], Wp1[32];
    {
        const ull* w0p = (const ull*)(W_hh + (size_t)(j0 + 2 * l) * HH + w * 64);
        const ull* w1p = (const ull*)(W_hh + (size_t)(j0 + 2 * l + 1) * HH + w * 64);
#pragma unroll
        for (int p = 0; p < 32; p++) { Wp0[p] = w0p[p]; Wp1[p] = w1p[p]; }
    }
    const float bh = b_hh[gj];

    // ---- init h slot 0 of both groups from h0 ----
#pragma unroll
    for (int g = 0; g < 2; g++) {
        float* hf = (float*)&hsp[g][0][0][0];
        for (int i = tid; i < 2 * HH; i += 256) {
            int b = i >> 9, k = i & 511;
            hf[(k >> 1) * 4 + b * 2 + (k & 1)] = h0[(size_t)(b0 + 2 * g + b) * HH + k];
        }
    }

    const uint32_t mb_local = smem_u32(&mbars[0]);
    if (tid == 0) {
#pragma unroll
        for (int i = 0; i < 8; i++) {
            mbar_init(mb_local + 8 * i, 1);
            mbar_arrive_expect_tx(mb_local + 8 * i, (i & 1) ? 2048u : 1536u);
        }
        asm volatile("fence.mbarrier_init.release.cluster;" ::: "memory");
    }
    __syncthreads();
    asm volatile("barrier.cluster.arrive.aligned;" ::: "memory");
    asm volatile("barrier.cluster.wait.aligned;" ::: "memory");

    // remote addresses
    const uint32_t hbase = smem_u32(&hsp[0][0][0][0]);
    const uint32_t off_self = rank * 512u;
    const uint32_t off_quad = (rank & ~3u) * 512u;
    // hop1 peer for tids 0..2: rank ^ (tid+1); others get a dummy (unused)
    const uint32_t p1 = rank ^ (uint32_t)((tid < 3) ? (tid + 1) : 1);
    const uint32_t hQ = mapa_rank(hbase, p1), mQ = mapa_rank(mb_local, p1);
    // hop2 mirror
    const uint32_t hO = mapa_rank(hbase, rank ^ 4u);
    const uint32_t mO = mapa_rank(mb_local, rank ^ 4u);
    // staging index of this thread's hv inside the own 512B slice (floats)
    const int sidx = (oj >> 1) * 4 + obl * 2 + (oj & 1);

    const size_t obA = (size_t)(b0 + obl) * SS * HH + gj;
    const size_t obB = (size_t)(b0 + 2 + obl) * SS * HH + gj;
    float xpA = 0.f, xpB = 0.f, hlA = 0.f, hlB = 0.f;
    if (tid < 128) { xpA = __ldcs(out + obA); xpB = __ldcs(out + obB); }
    uint32_t phA0 = 0, phA1 = 0, phB0 = 0, phB1 = 0;

#define GSTEP(T, S, G, PH, XP, HL, OB)                                          \
  {                                                                             \
    if ((T) > 0) {                                                              \
      mbar_wait_cluster(mb_local + MBOFF(G, S, 0), PH);                         \
      mbar_wait_cluster(mb_local + MBOFF(G, S, 1), PH);                         \
      PH ^= 1u;                                                                 \
      if (tid == 0) {                                                           \
        mbar_arrive_expect_tx(mb_local + MBOFF(G, S, 0), 1536u);                \
        mbar_arrive_expect_tx(mb_local + MBOFF(G, S, 1), 2048u);                \
      }                                                                         \
    }                                                                           \
    const ull* hb = &hsp[G][S][w * 32][0];                                      \
    ull a00 = 0, a01 = 0, a10 = 0, a11 = 0;                                     \
    _Pragma("unroll")                                                           \
    for (int p = 0; p < 32; p++) {                                              \
      ulonglong2 hx = *(const ulonglong2*)(hb + p * 2);                         \
      ull w0 = Wp0[p], w1 = Wp1[p];                                             \
      ffma2(a00, hx.x, w0); ffma2(a01, hx.y, w0);                               \
      ffma2(a10, hx.x, w1); ffma2(a11, hx.y, w1);                               \
    }                                                                           \
    { float2 f; float2 ra, rb;                                                  \
      f = unpack2(a00); ra.x = f.x + f.y; f = unpack2(a01); ra.y = f.x + f.y;   \
      f = unpack2(a10); rb.x = f.x + f.y; f = unpack2(a11); rb.y = f.x + f.y;   \
      *(float2*)&red[G][0][w][l][0] = ra;                                       \
      *(float2*)&red[G][1][w][l][0] = rb; }                                     \
    __syncthreads();                                                            \
    float hv = 0.f;                                                             \
    if (tid < 128) {                                                            \
      const float* rf = &red[G][oj & 1][0][oj >> 1][obl];                       \
      float sum = rf[0] + rf[64] + rf[128] + rf[192]                            \
                + rf[256] + rf[320] + rf[384] + rf[448];                        \
      float pre = XP + sum + bh;                                                \
      float e = __expf(pre + pre);                                              \
      hv = 1.f - __fdividef(2.f, e + 1.f);                                      \
      if ((T) + 1 < SS)                                                         \
        ((float*)&hsp[0][0][0][0])[(BLK(G, (S) ^ 1) + off_self) / 4 + sidx] = hv;\
    }                                                                           \
    __syncthreads();                                                            \
    if (((T) + 1 < SS) && tid < 3) {                                            \
      fence_pa();                                                               \
      bulk_copy_cluster(hQ + BLK(G, (S) ^ 1) + off_self,                        \
                        hbase + BLK(G, (S) ^ 1) + off_self, 512u,               \
                        mQ + MBOFF(G, (S) ^ 1, 0));                             \
    }                                                                           \
    if (tid < 128) {                                                            \
      __stcs(out + OB + (size_t)(T) * HH, hv);                                  \
      HL = hv;                                                                  \
      if ((T) + 1 < SS) XP = __ldcs(out + OB + (size_t)((T) + 1) * HH);         \
    }                                                                           \
  }

// hop2 forward for the exchange targeting slot SP (both groups), tid0 only.
#define FWD(T, SP, PHA, PHB)                                                    \
  if (((T) + 1 < SS) && tid == 0) {                                             \
    mbar_wait_cluster(mb_local + MBOFF(0, SP, 0), PHA);                         \
    fence_pa();                                                                 \
    bulk_copy_cluster(hO + BLK(0, SP) + off_quad,                               \
                      hbase + BLK(0, SP) + off_quad, 2048u,                     \
                      mO + MBOFF(0, SP, 1));                                    \
    mbar_wait_cluster(mb_local + MBOFF(1, SP, 0), PHB);                         \
    fence_pa();                                                                 \
    bulk_copy_cluster(hO + BLK(1, SP) + off_quad,                               \
                      hbase + BLK(1, SP) + off_quad, 2048u,                     \
                      mO + MBOFF(1, SP, 1));                                    \
  }

    for (int t = 0; t < SS; t += 2) {
        GSTEP(t,     0, 0, phA0, xpA, hlA, obA);
        GSTEP(t,     0, 1, phB0, xpB, hlB, obB);
        FWD(t, 1, phA1, phB1);
        GSTEP(t + 1, 1, 0, phA1, xpA, hlA, obA);
        GSTEP(t + 1, 1, 1, phB1, xpB, hlB, obB);
        FWD(t + 1, 0, phA0, phB0);
    }
#undef GSTEP
#undef FWD

    if (write_hfinal && tid < 128) {
        out[(size_t)BB * SS * HH + (size_t)(b0 + obl) * HH + gj] = hlA;
        out[(size_t)BB * SS * HH + (size_t)(b0 + 2 + obl) * HH + gj] = hlB;
    }
    asm volatile("barrier.cluster.arrive.aligned;" ::: "memory");
    asm volatile("barrier.cluster.wait.aligned;" ::: "memory");
}

// ---------------- launch ----------------
extern "C" void kernel_launch(void* const* d_in, const int* in_sizes, int n_in,
                              void* d_out, int out_size) {
    const float* inputs = (const float*)d_in[0];   // [64, 2048, 512]
    const float* h0     = (const float*)d_in[1];   // [64, 512]
    const float* W_ih   = (const float*)d_in[2];   // [512, 512]
    const float* W_hh   = (const float*)d_in[3];   // [512, 512]
    const float* b_ih   = (const float*)d_in[4];   // [512]
    const float* b_hh   = (const float*)d_in[5];   // [512]
    float* out = (float*)d_out;

    // Phase 1: x_proj into the outs region of d_out (scan overwrites in place)
    dim3 g1((BB * SS) / 128, HH / 128, 1);
    xproj_kernel<<<g1, 256>>>(inputs, W_ih, b_ih, out);

    // Phase 2: 16 clusters of 8 CTAs; radix-4+2 all-gather scan
    long long need = (long long)BB * SS * HH + (long long)BB * HH;
    int wf = ((long long)out_size >= need) ? 1 : 0;
    rnn_scan_kernel<<<NCTA, 256>>>(h0, W_hh, b_hh, out, wf);
}